// round 6
// baseline (speedup 1.0000x reference)
#include <cuda_runtime.h>
#include <stdint.h>

// Problem constants
#define VS 64
#define DEPTH_HW 256
#define IMG_H 1024
#define IMG_W 1280
#define BATCH 8
#define OUT_PER_B (VS * VS * VS)           // 262144 voxels per batch
#define N_OUT (BATCH * OUT_PER_B)          // 2097152 floats out
#define NWORD (OUT_PER_B / 4)              // 65536 words per replica
#define R 16                               // replicas (break hot-address atomic serialization)

// Bit layout: word w covers voxels lin = 4w..4w+3 (one x,y column z-group)
// across ALL 8 batches: bit = (lin&3)*8 + b. A word maps 1:1 onto one output
// float4 per batch, making the expand pass fully coalesced.
// 16 replicas x 256KB = 4MB. Zeroed at module load; expand restores zero
// every call so each kernel_launch / graph replay starts clean.
__device__ unsigned g_bits[R][NWORD];

// Scatter: one thread per non-padded pixel; warp covers a 4(y) x 8(x) tile
// so the per-batch depth load is 1-2 cache lines. Tight inline loop (the
// best-measured shape): load depth, compute voxel, REDG.OR into this warp's
// replica. No per-thread arrays, no merge logic.
__global__ void __launch_bounds__(256)
vox_scatter_kernel(const float* __restrict__ depth,   // [8,256,256]
                   const float* __restrict__ ray)     // [1280*1024, 3]
{
    const int lane = threadIdx.x & 31;
    const int wid  = threadIdx.x >> 5;            // 0..7
    const int bx   = blockIdx.x & 127;            // 128 x-tiles of width 8
    const int by   = blockIdx.x >> 7;             // 32  y-tiles of height 32

    const int y  = by * 32 + wid * 4 + (lane & 3);   // 0..1023
    const int xr = bx * 8 + (lane >> 2);             // 0..1023 (non-padded x)

    unsigned* __restrict__ bits = g_bits[((blockIdx.x << 3) + wid) & (R - 1)];

    // ray index: column-major flatten idx = x*1024 + y, x = xr + 128
    const int ridx = ((xr + 128) << 10) + y;
    const float rx = __ldg(&ray[3 * ridx + 0]);
    const float ry = __ldg(&ray[3 * ridx + 1]);
    const float rz = __ldg(&ray[3 * ridx + 2]);

    const float scale = 64.0f / 3.0f;
    const int doff = ((y >> 2) << 8) + (xr >> 2);    // depth[b, y/4, xr/4]

#pragma unroll
    for (int b = 0; b < BATCH; b++) {
        const float d = __ldg(&depth[b * (DEPTH_HW * DEPTH_HW) + doff]);

        // Replicate reference f32 op sequence exactly: mul, add, mul,
        // round-half-even. _rn intrinsics forbid FFMA contraction.
        const float px = __fmul_rn(rx, d);
        const float py = __fmul_rn(ry, d);
        const float pz = __fmul_rn(rz, d);

        const int ix = __float2int_rn(__fmul_rn(__fadd_rn(px, 1.5f), scale));
        const int iy = __float2int_rn(__fmul_rn(__fadd_rn(py, 1.5f), scale));
        const int iz = __float2int_rn(__fmul_rn(pz, scale));

        if (((unsigned)ix < 64u) & ((unsigned)iy < 64u) & ((unsigned)iz < 64u)) {
            const int lin = (((ix << 6) + iy) << 6) + iz;
            atomicOr(&bits[lin >> 2], 1u << (((lin & 3) << 3) + b));
        }
    }

    // Padded columns all have depth==0 -> voxel (32,32,0) for every batch:
    // lin = 133120 -> word 33280, z-offset 0, all 8 batch bits at once.
    if (blockIdx.x == 0 && threadIdx.x == 0) {
        atomicOr(&g_bits[0][33280], 0xFFu);
    }
}

// Expand: two threads per word (131072 threads). Even lane ORs replicas
// 0..7, odd lane ORs replicas 8..15; shfl_xor(1) combines. Each lane then
// emits 4 coalesced float4 stores (4 batches) and zeroes its own 8 replica
// words (loads precede stores in program order; each lane owns its replica
// half exclusively). Writes every output element, so no separate zero pass.
__global__ void __launch_bounds__(256)
vox_expand_kernel(float4* __restrict__ out)
{
    const int tid  = blockIdx.x * 256 + threadIdx.x;  // 0 .. 2*NWORD-1
    const int w    = tid >> 1;
    const int half = tid & 1;                          // 0: replicas 0-7, 1: 8-15
    const int rb   = half << 3;                        // replica base

    unsigned v = 0;
#pragma unroll
    for (int r = 0; r < 8; r++) v |= g_bits[rb + r][w];

    // Combine halves within the lane pair (lane^1 holds the same word).
    v |= __shfl_xor_sync(0xFFFFFFFFu, v, 1);

    const int bb = half << 2;                          // batch base: 0 or 4
#pragma unroll
    for (int k = 0; k < 4; k++) {
        const int b = bb + k;
        float4 o;
        o.x = ((v >> (0 * 8 + b)) & 1u) ? 1.0f : 0.0f;
        o.y = ((v >> (1 * 8 + b)) & 1u) ? 1.0f : 0.0f;
        o.z = ((v >> (2 * 8 + b)) & 1u) ? 1.0f : 0.0f;
        o.w = ((v >> (3 * 8 + b)) & 1u) ? 1.0f : 0.0f;
        out[b * NWORD + w] = o;
    }

#pragma unroll
    for (int r = 0; r < 8; r++) g_bits[rb + r][w] = 0u;
}

extern "C" void kernel_launch(void* const* d_in, const int* in_sizes, int n_in,
                              void* d_out, int out_size)
{
    const float* depth = (const float*)d_in[0];
    const float* ray   = (const float*)d_in[1];
    // Defensive: identify by element count (depth = 524288, ray = 3932160)
    if (n_in >= 2 && in_sizes[0] == IMG_W * IMG_H * 3) {
        ray   = (const float*)d_in[0];
        depth = (const float*)d_in[1];
    }
    float* out = (float*)d_out;

    vox_scatter_kernel<<<4096, 256>>>(depth, ray);
    vox_expand_kernel<<<(2 * NWORD) / 256, 256>>>((float4*)out);
}

// round 7
// speedup vs baseline: 1.3154x; 1.3154x over previous
#include <cuda_runtime.h>
#include <stdint.h>

// Problem constants
#define VS 64
#define DEPTH_HW 256
#define IMG_H 1024
#define IMG_W 1280
#define BATCH 8
#define OUT_PER_B (VS * VS * VS)           // 262144 voxels per batch
#define N_OUT (BATCH * OUT_PER_B)          // 2097152 floats out
#define NBW (OUT_PER_B / 32)               // 8192 bit-words per batch
#define NW  (BATCH * NBW)                  // 65536 words per replica
#define R   16                             // replicas (break hot-address atomic serialization)

// Per-batch bit grids (word address includes the batch index -- this spreads
// the hot near-origin voxel mass over 8x more addresses; measured essential).
// 16 replicas x 256KB = 4MB. Zeroed at module load; the expand kernel
// restores zero every call, so each kernel_launch / graph replay starts clean.
__device__ unsigned g_bits[R][NW];

// Scatter: one thread per non-padded pixel; warp covers a 4(y) x 8(x) tile so
// each per-batch depth load is a single 128B line. Tight inline loop
// (measured-best shape): load depth, compute voxel, REDG.OR into this warp's
// replica. No per-thread arrays, no merge logic.
__global__ void __launch_bounds__(256)
vox_scatter_kernel(const float* __restrict__ depth,   // [8,256,256]
                   const float* __restrict__ ray)     // [1280*1024, 3]
{
    const int lane = threadIdx.x & 31;
    const int wid  = threadIdx.x >> 5;            // 0..7
    const int bx   = blockIdx.x & 127;            // 128 x-tiles of width 8
    const int by   = blockIdx.x >> 7;             // 32  y-tiles of height 32

    const int y  = by * 32 + wid * 4 + (lane & 3);   // 0..1023
    const int xr = bx * 8 + (lane >> 2);             // 0..1023 (non-padded x)

    unsigned* __restrict__ bits = g_bits[((blockIdx.x << 3) + wid) & (R - 1)];

    // ray index: column-major flatten idx = x*1024 + y, x = xr + 128
    const int ridx = ((xr + 128) << 10) + y;
    const float rx = __ldg(&ray[3 * ridx + 0]);
    const float ry = __ldg(&ray[3 * ridx + 1]);
    const float rz = __ldg(&ray[3 * ridx + 2]);

    const float scale = 64.0f / 3.0f;
    const int doff = ((y >> 2) << 8) + (xr >> 2);    // depth[b, y/4, xr/4]

#pragma unroll
    for (int b = 0; b < BATCH; b++) {
        const float d = __ldg(&depth[b * (DEPTH_HW * DEPTH_HW) + doff]);

        // Replicate reference f32 op sequence exactly: mul, add, mul,
        // round-half-even. _rn intrinsics forbid FFMA contraction.
        const float px = __fmul_rn(rx, d);
        const float py = __fmul_rn(ry, d);
        const float pz = __fmul_rn(rz, d);

        const int ix = __float2int_rn(__fmul_rn(__fadd_rn(px, 1.5f), scale));
        const int iy = __float2int_rn(__fmul_rn(__fadd_rn(py, 1.5f), scale));
        const int iz = __float2int_rn(__fmul_rn(pz, scale));

        if (((unsigned)ix < 64u) & ((unsigned)iy < 64u) & ((unsigned)iz < 64u)) {
            const int lin = (((ix << 6) + iy) << 6) + iz;
            atomicOr(&bits[b * NBW + (lin >> 5)], 1u << (lin & 31));
        }
    }

    // Padded columns all have depth==0 -> voxel (32,32,0), lin = 133120
    // = word 4160, bit 0, for every batch. Write into replica 0.
    if (blockIdx.x == 0 && threadIdx.x < BATCH) {
        atomicOr(&g_bits[0][threadIdx.x * NBW + 4160], 1u);
    }
}

// Expand: 8 consecutive threads share one bit-word (words never span warps
// since 8 | 32). Each lane loads only TWO replicas of the word; a 3-step
// shfl_xor OR-butterfly across the 8-lane subgroup gives every lane the full
// 16-replica OR. Each lane then emits one coalesced float4 (its 4 bits) and
// zeroes its own 2 replica words (loads precede stores in program order;
// each lane's stores touch only words it alone loaded... all subgroup lanes
// loaded distinct replicas, and shuffles consume register values, so the
// zeroing cannot race with any load). Writes every output element, so no
// separate zero pass is needed.
__global__ void __launch_bounds__(256)
vox_expand_kernel(float4* __restrict__ out)
{
    const int tid = blockIdx.x * 256 + threadIdx.x;   // 0 .. N_OUT/4 - 1
    const int w   = tid >> 3;
    const int s   = tid & 7;                           // subgroup lane
    const int r0  = s << 1;                            // replica pair base

    unsigned v = g_bits[r0][w] | g_bits[r0 + 1][w];

    // OR-reduce across the 8-lane subgroup (same word w in all 8 lanes).
    v |= __shfl_xor_sync(0xFFFFFFFFu, v, 1);
    v |= __shfl_xor_sync(0xFFFFFFFFu, v, 2);
    v |= __shfl_xor_sync(0xFFFFFFFFu, v, 4);

    const unsigned sh = s * 4;
    float4 o;
    o.x = ((v >> (sh + 0)) & 1u) ? 1.0f : 0.0f;
    o.y = ((v >> (sh + 1)) & 1u) ? 1.0f : 0.0f;
    o.z = ((v >> (sh + 2)) & 1u) ? 1.0f : 0.0f;
    o.w = ((v >> (sh + 3)) & 1u) ? 1.0f : 0.0f;
    out[tid] = o;

    g_bits[r0][w]     = 0u;
    g_bits[r0 + 1][w] = 0u;
}

extern "C" void kernel_launch(void* const* d_in, const int* in_sizes, int n_in,
                              void* d_out, int out_size)
{
    const float* depth = (const float*)d_in[0];
    const float* ray   = (const float*)d_in[1];
    // Defensive: identify by element count (depth = 524288, ray = 3932160)
    if (n_in >= 2 && in_sizes[0] == IMG_W * IMG_H * 3) {
        ray   = (const float*)d_in[0];
        depth = (const float*)d_in[1];
    }
    float* out = (float*)d_out;

    vox_scatter_kernel<<<4096, 256>>>(depth, ray);
    vox_expand_kernel<<<(N_OUT / 4) / 256, 256>>>((float4*)out);
}

// round 8
// speedup vs baseline: 1.3563x; 1.0311x over previous
#include <cuda_runtime.h>
#include <stdint.h>

// Problem constants
#define VS 64
#define DEPTH_HW 256
#define IMG_H 1024
#define IMG_W 1280
#define BATCH 8
#define OUT_PER_B (VS * VS * VS)           // 262144 voxels per batch
#define N_OUT (BATCH * OUT_PER_B)          // 2097152 floats out
#define NBW (OUT_PER_B / 32)               // 8192 bit-words per batch
#define NW  (BATCH * NBW)                  // 65536 words per replica
#define R   16                             // replicas (break hot-address atomic serialization)

// Per-batch bit grids (word address includes the batch index -- spreads the
// hot near-origin voxel mass over 8x more addresses; measured essential).
// 16 replicas x 256KB = 4MB. Zeroed at module load; the expand kernel
// restores zero every call, so each kernel_launch / graph replay starts clean.
__device__ unsigned g_bits[R][NW];

// Scatter (FROZEN at measured-best shape): one thread per non-padded pixel;
// warp covers a 4(y) x 8(x) tile so each per-batch depth load is a single
// 128B line. Tight inline loop: load depth, compute voxel, REDG.OR into this
// warp's replica. At the REDG lane-throughput floor.
__global__ void __launch_bounds__(256)
vox_scatter_kernel(const float* __restrict__ depth,   // [8,256,256]
                   const float* __restrict__ ray)     // [1280*1024, 3]
{
    const int lane = threadIdx.x & 31;
    const int wid  = threadIdx.x >> 5;            // 0..7
    const int bx   = blockIdx.x & 127;            // 128 x-tiles of width 8
    const int by   = blockIdx.x >> 7;             // 32  y-tiles of height 32

    const int y  = by * 32 + wid * 4 + (lane & 3);   // 0..1023
    const int xr = bx * 8 + (lane >> 2);             // 0..1023 (non-padded x)

    unsigned* __restrict__ bits = g_bits[((blockIdx.x << 3) + wid) & (R - 1)];

    // ray index: column-major flatten idx = x*1024 + y, x = xr + 128
    const int ridx = ((xr + 128) << 10) + y;
    const float rx = __ldg(&ray[3 * ridx + 0]);
    const float ry = __ldg(&ray[3 * ridx + 1]);
    const float rz = __ldg(&ray[3 * ridx + 2]);

    const float scale = 64.0f / 3.0f;
    const int doff = ((y >> 2) << 8) + (xr >> 2);    // depth[b, y/4, xr/4]

#pragma unroll
    for (int b = 0; b < BATCH; b++) {
        const float d = __ldg(&depth[b * (DEPTH_HW * DEPTH_HW) + doff]);

        // Replicate reference f32 op sequence exactly: mul, add, mul,
        // round-half-even. _rn intrinsics forbid FFMA contraction.
        const float px = __fmul_rn(rx, d);
        const float py = __fmul_rn(ry, d);
        const float pz = __fmul_rn(rz, d);

        const int ix = __float2int_rn(__fmul_rn(__fadd_rn(px, 1.5f), scale));
        const int iy = __float2int_rn(__fmul_rn(__fadd_rn(py, 1.5f), scale));
        const int iz = __float2int_rn(__fmul_rn(pz, scale));

        if (((unsigned)ix < 64u) & ((unsigned)iy < 64u) & ((unsigned)iz < 64u)) {
            const int lin = (((ix << 6) + iy) << 6) + iz;
            atomicOr(&bits[b * NBW + (lin >> 5)], 1u << (lin & 31));
        }
    }

    // Padded columns all have depth==0 -> voxel (32,32,0), lin = 133120
    // = word 4160, bit 0, for every batch. Write into replica 0.
    if (blockIdx.x == 0 && threadIdx.x < BATCH) {
        atomicOr(&g_bits[0][threadIdx.x * NBW + 4160], 1u);
    }
}

// Expand: each warp owns 32 consecutive words exclusively (all replicas).
// Lane l accumulates word w0+l over all 16 replicas -- every load is one
// fully-coalesced 128B line per warp. Zeroing mirrors the loads (16 coalesced
// stores; loads precede stores in program order, exclusive ownership => no
// race). Output: 8 rounds; round j fetches the source word via shfl (src
// lane 4j + l/8), extracts this lane's 4-bit nibble, writes one coalesced
// float4. Word w maps to output float4s [8w, 8w+8) because out is
// [B][VS^3] = [NW*32] floats and w already encodes the batch.
// Writes every output element, so no separate zero pass.
__global__ void __launch_bounds__(256)
vox_expand_kernel(float4* __restrict__ out)
{
    const int lane  = threadIdx.x & 31;
    const int warp  = (blockIdx.x * 256 + threadIdx.x) >> 5;  // 0..2047
    const int w0    = warp * 32;

    unsigned acc = 0;
#pragma unroll
    for (int r = 0; r < R; r++) acc |= g_bits[r][w0 + lane];

#pragma unroll
    for (int r = 0; r < R; r++) g_bits[r][w0 + lane] = 0u;

    const unsigned sh = (lane & 7) * 4;
#pragma unroll
    for (int j = 0; j < 8; j++) {
        const unsigned v = __shfl_sync(0xFFFFFFFFu, acc, j * 4 + (lane >> 3));
        float4 o;
        o.x = ((v >> (sh + 0)) & 1u) ? 1.0f : 0.0f;
        o.y = ((v >> (sh + 1)) & 1u) ? 1.0f : 0.0f;
        o.z = ((v >> (sh + 2)) & 1u) ? 1.0f : 0.0f;
        o.w = ((v >> (sh + 3)) & 1u) ? 1.0f : 0.0f;
        out[w0 * 8 + j * 32 + lane] = o;
    }
}

extern "C" void kernel_launch(void* const* d_in, const int* in_sizes, int n_in,
                              void* d_out, int out_size)
{
    const float* depth = (const float*)d_in[0];
    const float* ray   = (const float*)d_in[1];
    // Defensive: identify by element count (depth = 524288, ray = 3932160)
    if (n_in >= 2 && in_sizes[0] == IMG_W * IMG_H * 3) {
        ray   = (const float*)d_in[0];
        depth = (const float*)d_in[1];
    }
    float* out = (float*)d_out;

    vox_scatter_kernel<<<4096, 256>>>(depth, ray);
    // 65536 words / 32 per warp = 2048 warps = 256 blocks of 256 threads
    vox_expand_kernel<<<256, 256>>>((float4*)out);
}